// round 11
// baseline (speedup 1.0000x reference)
#include <cuda_runtime.h>
#include <cuda_bf16.h>
#include <math.h>

// Problem constants
#define BB 2
#define SS 1024
#define DD 768
#define HH 12
#define HDIM 64
#define EE 8
#define TOPK 2
#define FF 3072
#define NTOK (BB*SS)        // 2048
#define D3 (3*DD)           // 2304
#define NPAIR (NTOK*TOPK)   // 4096

// ---------------- device scratch ----------------
__device__ __nv_bfloat16 g_xln1b[NTOK*DD];
__device__ __nv_bfloat16 g_qkvb [NTOK*D3];
__device__ __nv_bfloat16 g_ctxb [NTOK*DD];
__device__ float         g_hs   [NTOK*DD];
__device__ float         g_x2   [NTOK*DD];
__device__ __nv_bfloat16 g_x2b  [NTOK*DD];
__device__ __nv_bfloat16 g_hb   [NPAIR*FF];
// bf16 weight caches (converted once per launch)
__device__ __nv_bfloat16 g_wattnb [DD*D3];
__device__ __nv_bfloat16 g_waprojb[DD*DD];
__device__ __nv_bfloat16 g_wfcb   [EE*DD*FF];
__device__ __nv_bfloat16 g_wprojb [EE*FF*DD];
__device__ int   g_topidx[NTOK*TOPK];
__device__ float g_topw [NTOK*TOPK];
__device__ int   g_counts[EE];
__device__ int   g_offsets[EE+1];
__device__ int   g_cursor[EE];
__device__ int   g_pairtok[NPAIR];
__device__ float g_pairw [NPAIR];

// ---------------- helpers ----------------
__device__ __forceinline__ void mma_bf16(float c[4], unsigned a0, unsigned a1,
                                         unsigned a2, unsigned a3,
                                         unsigned b0, unsigned b1) {
    asm volatile(
        "mma.sync.aligned.m16n8k16.row.col.f32.bf16.bf16.f32 "
        "{%0,%1,%2,%3},{%4,%5,%6,%7},{%8,%9},{%0,%1,%2,%3};"
        : "+f"(c[0]), "+f"(c[1]), "+f"(c[2]), "+f"(c[3])
        : "r"(a0), "r"(a1), "r"(a2), "r"(a3), "r"(b0), "r"(b1));
}
__device__ __forceinline__ void ldsm4(unsigned& r0, unsigned& r1, unsigned& r2,
                                      unsigned& r3, unsigned a) {
    asm volatile("ldmatrix.sync.aligned.m8n8.x4.shared.b16 {%0,%1,%2,%3},[%4];"
                 : "=r"(r0), "=r"(r1), "=r"(r2), "=r"(r3) : "r"(a));
}
__device__ __forceinline__ void ldsm4t(unsigned& r0, unsigned& r1, unsigned& r2,
                                       unsigned& r3, unsigned a) {
    asm volatile("ldmatrix.sync.aligned.m8n8.x4.trans.shared.b16 {%0,%1,%2,%3},[%4];"
                 : "=r"(r0), "=r"(r1), "=r"(r2), "=r"(r3) : "r"(a));
}
__device__ __forceinline__ void cp16(void* smem_dst, const void* gsrc, bool valid) {
    unsigned dst = (unsigned)__cvta_generic_to_shared(smem_dst);
    int sz = valid ? 16 : 0;
    asm volatile("cp.async.cg.shared.global [%0], [%1], 16, %2;"
                 :: "r"(dst), "l"(gsrc), "r"(sz));
}
__device__ __forceinline__ void cp_commit() {
    asm volatile("cp.async.commit_group;");
}
__device__ __forceinline__ void cp_wait0() {
    asm volatile("cp.async.wait_group 0;" ::: "memory");
}
__device__ __forceinline__ void cp_wait1() {
    asm volatile("cp.async.wait_group 1;" ::: "memory");
}

// ---------------- fp32 -> bf16 weight conversion (grid-stride, MLP 4) ----------------
__global__ void cvt_bf16(const float4* __restrict__ src, uint2* __restrict__ dst, int n4) {
    int stride = gridDim.x * blockDim.x;
#pragma unroll 4
    for (int i = blockIdx.x*blockDim.x + threadIdx.x; i < n4; i += stride) {
        float4 a = src[i];
        __nv_bfloat162 h0 = __floats2bfloat162_rn(a.x, a.y);
        __nv_bfloat162 h1 = __floats2bfloat162_rn(a.z, a.w);
        dst[i] = make_uint2(*(unsigned*)&h0, *(unsigned*)&h1);
    }
}

// ---------------- LayerNorm (fp32 in; optional fp32 out + bf16 out) ----------------
__global__ void ln_kernel(const float* __restrict__ x,
                          const float* __restrict__ g,
                          const float* __restrict__ b,
                          float* __restrict__ outf,
                          __nv_bfloat16* __restrict__ outb) {
    int row = blockIdx.x;
    int tid = threadIdx.x;
    const float* xr = x + (size_t)row*DD;
    float v[3];
    float s = 0.f, s2 = 0.f;
#pragma unroll
    for (int i = 0; i < 3; i++) {
        v[i] = xr[tid + i*256];
        s += v[i]; s2 += v[i]*v[i];
    }
    __shared__ float2 red[256];
    red[tid] = make_float2(s, s2);
    __syncthreads();
    for (int off = 128; off > 0; off >>= 1) {
        if (tid < off) {
            red[tid].x += red[tid+off].x;
            red[tid].y += red[tid+off].y;
        }
        __syncthreads();
    }
    float mu  = red[0].x * (1.0f/DD);
    float var = red[0].y * (1.0f/DD) - mu*mu;
    float inv = rsqrtf(var + 1e-5f);
#pragma unroll
    for (int i = 0; i < 3; i++) {
        int c = tid + i*256;
        float val = (v[i] - mu) * inv * g[c] + b[c];
        if (outf) outf[(size_t)row*DD + c] = val;
        outb[(size_t)row*DD + c] = __float2bfloat16(val);
    }
}

// ---------------- bf16 MMA GEMM: k-step 32, ldmatrix frags, 3-stage cp.async --------
// MODE 0: Cb = bf16(A@B + bias)                  (QKV)
// MODE 1: C = A@B + bias + resid; C2 = C (fp32)  (attn out proj + out init)
// MODE 2: Cb = bf16(gelu(gather(A)@B[e]+bias))   (MoE FC)
// MODE 3: atomic C[tok] += w*(A@B[e]+bias[e])    (MoE PROJ)
template<int MODE, int TM, int TN>
__global__ void __launch_bounds__(256)
mma_gemm(const __nv_bfloat16* __restrict__ A, const __nv_bfloat16* __restrict__ B,
         const float* __restrict__ bias, const float* __restrict__ resid,
         void* __restrict__ Cv, float* __restrict__ C2, int M, int N, int K) {
    constexpr int MI = TM/32;          // m16 tiles per warp
    constexpr int NI = TN/32;          // n8 tiles per warp
    constexpr int WCOL = TN/4;         // warp col span
    constexpr int APAD = 40;           // bf16 per A row (80B: odd 16B units)
    constexpr int BPAD = TN + 8;       // bf16 per B row (odd 16B units)
    constexpr int ASTRIDE = TM*APAD;
    constexpr int BSTRIDE = 32*BPAD;
    constexpr int ACT = TM*4/256;      // A 16B chunks per thread per stage
    constexpr int BCT = TN*4/256;      // B 16B chunks per thread per stage

    int e = 0, seg = 0, cnt = M;
    if (MODE >= 2) {
        e = blockIdx.z;
        seg = g_offsets[e];
        cnt = g_offsets[e+1] - seg;
    }
    int rowBase = blockIdx.y * TM;
    if (rowBase >= cnt) return;
    int colBase = blockIdx.x * TN;
    const __nv_bfloat16* Bm = B + (size_t)e*K*N;
    const float* biasv = bias + (size_t)e*N;

    extern __shared__ __nv_bfloat16 smemb[];
    __nv_bfloat16* Asm = smemb;                 // 3 stages [TM][APAD]
    __nv_bfloat16* Bsm = smemb + 3*ASTRIDE;     // 3 stages [32][BPAD]
    __shared__ int sTok[TM];

    int tid = threadIdx.x;
    int lane = tid & 31, warp = tid >> 5;
    int wy = warp >> 2, wx = warp & 3;
    int g4 = lane >> 2, t4 = lane & 3;

    if (MODE == 2) {
        for (int i = tid; i < TM; i += 256)
            sTok[i] = (rowBase + i < cnt) ? g_pairtok[seg + rowBase + i] : -1;
        __syncthreads();
    }

    // A chunk coords
    int arow[ACT], akh[ACT];
    const __nv_bfloat16* aptr[ACT];
    bool avalid[ACT];
#pragma unroll
    for (int l = 0; l < ACT; l++) {
        int idx = tid + l*256;
        arow[l] = idx >> 2; akh[l] = (idx & 3) * 8;
        if (MODE == 2) {
            int tk = sTok[arow[l]];
            avalid[l] = (tk >= 0);
            aptr[l] = A + (avalid[l] ? (size_t)tk*K : 0) + akh[l];
        } else if (MODE == 3) {
            avalid[l] = (rowBase + arow[l] < cnt);
            aptr[l] = A + (avalid[l] ? (size_t)(seg + rowBase + arow[l])*K : 0) + akh[l];
        } else {
            avalid[l] = true;
            aptr[l] = A + (size_t)(rowBase + arow[l])*K + akh[l];
        }
    }
    // B chunk coords: 32 rows x TN cols bf16
    int brow[BCT], bseg[BCT];
    const __nv_bfloat16* bptr[BCT];
#pragma unroll
    for (int l = 0; l < BCT; l++) {
        int idx = tid + l*256;
        brow[l] = idx / (TN/8); bseg[l] = (idx % (TN/8)) * 8;
        bptr[l] = Bm + (size_t)brow[l]*N + colBase + bseg[l];
    }

    float acc[MI][NI][4] = {};
    int nt = K / 32;

    // prologue: tiles 0 and 1
#pragma unroll
    for (int p = 0; p < 2; p++) {
        int k0 = p * 32;
#pragma unroll
        for (int l = 0; l < ACT; l++)
            cp16(&Asm[p*ASTRIDE + arow[l]*APAD + akh[l]], aptr[l] + k0, avalid[l]);
#pragma unroll
        for (int l = 0; l < BCT; l++)
            cp16(&Bsm[p*BSTRIDE + brow[l]*BPAD + bseg[l]], bptr[l] + (size_t)k0*N, true);
        cp_commit();
    }

    // ldmatrix lane addressing
    int lrow = lane & 15;
    int lcol = (lane >> 4) * 8;

    for (int kt = 0; kt < nt; kt++) {
        if (kt + 1 < nt) cp_wait1(); else cp_wait0();
        __syncthreads();
        if (kt + 2 < nt) {
            int st = (kt + 2) % 3;
            int k0 = (kt + 2) * 32;
#pragma unroll
            for (int l = 0; l < ACT; l++)
                cp16(&Asm[st*ASTRIDE + arow[l]*APAD + akh[l]], aptr[l] + k0, avalid[l]);
#pragma unroll
            for (int l = 0; l < BCT; l++)
                cp16(&Bsm[st*BSTRIDE + brow[l]*BPAD + bseg[l]], bptr[l] + (size_t)k0*N, true);
            cp_commit();
        }
        unsigned abase = (unsigned)__cvta_generic_to_shared(Asm + (kt % 3)*ASTRIDE);
        unsigned bbase = (unsigned)__cvta_generic_to_shared(Bsm + (kt % 3)*BSTRIDE);

#pragma unroll
        for (int ks = 0; ks < 32; ks += 16) {
            unsigned af[MI][4];
#pragma unroll
            for (int mi = 0; mi < MI; mi++) {
                unsigned addr = abase + ((wy*(TM/2) + mi*16 + lrow)*APAD + ks + lcol)*2;
                ldsm4(af[mi][0], af[mi][1], af[mi][2], af[mi][3], addr);
            }
            unsigned bf[NI][2];
#pragma unroll
            for (int nh = 0; nh < NI/2; nh++) {
                unsigned addr = bbase + ((ks + lrow)*BPAD + wx*WCOL + nh*16 + lcol)*2;
                ldsm4t(bf[nh*2][0], bf[nh*2][1], bf[nh*2+1][0], bf[nh*2+1][1], addr);
            }
#pragma unroll
            for (int mi = 0; mi < MI; mi++)
#pragma unroll
                for (int ni = 0; ni < NI; ni++)
                    mma_bf16(acc[mi][ni], af[mi][0], af[mi][1], af[mi][2], af[mi][3],
                             bf[ni][0], bf[ni][1]);
        }
    }

    // epilogue
    __nv_bfloat16* Cb = (__nv_bfloat16*)Cv;
    float* C = (float*)Cv;
#pragma unroll
    for (int mi = 0; mi < MI; mi++) {
#pragma unroll
        for (int ci = 0; ci < 2; ci++) {
            int r = wy*(TM/2) + mi*16 + g4 + ci*8;
            int grow = rowBase + r;
            if (grow >= cnt) continue;
#pragma unroll
            for (int ni = 0; ni < NI; ni++) {
                int col = colBase + wx*WCOL + ni*8 + t4*2;
                float v0 = acc[mi][ni][ci*2 + 0];
                float v1 = acc[mi][ni][ci*2 + 1];
                if (MODE == 0) {
                    v0 += biasv[col]; v1 += biasv[col+1];
                    *(__nv_bfloat162*)&Cb[(size_t)grow*N + col] = __floats2bfloat162_rn(v0, v1);
                } else if (MODE == 1) {
                    const float2 rr = *(const float2*)&resid[(size_t)grow*N + col];
                    v0 += biasv[col]   + rr.x;
                    v1 += biasv[col+1] + rr.y;
                    *(float2*)&C [(size_t)grow*N + col] = make_float2(v0, v1);
                    *(float2*)&C2[(size_t)grow*N + col] = make_float2(v0, v1);
                } else if (MODE == 2) {
                    v0 += biasv[col]; v1 += biasv[col+1];
                    v0 = 0.5f*v0*(1.0f + erff(v0*0.70710678118654752f));
                    v1 = 0.5f*v1*(1.0f + erff(v1*0.70710678118654752f));
                    *(__nv_bfloat162*)&Cb[(size_t)(seg + grow)*N + col] = __floats2bfloat162_rn(v0, v1);
                } else {
                    int p = seg + grow;
                    int tok = g_pairtok[p];
                    float pw = g_pairw[p];
                    atomicAdd(&C[(size_t)tok*N + col],   pw*(v0 + biasv[col]));
                    atomicAdd(&C[(size_t)tok*N + col+1], pw*(v1 + biasv[col+1]));
                }
            }
        }
    }
}

// ---------------- bf16 tensor-core attention (R8 form: single-buffer) ----------------
// 128 threads = 4 warps; warp owns 16 query rows. smem K/V/P tiles [64][72] bf16.
__global__ void __launch_bounds__(128) attn_mma() {
    extern __shared__ __nv_bfloat16 sm16[];
    __nv_bfloat16* sK = sm16;             // [64][72]
    __nv_bfloat16* sV = sm16 + 64*72;     // [64][72]
    __nv_bfloat16* sP = sm16 + 2*64*72;   // [64][72]
    const unsigned* sKw = (const unsigned*)sK;
    const unsigned* sPw = (const unsigned*)sP;
    const unsigned short* sVh = (const unsigned short*)sV;

    int tid = threadIdx.x;
    int lane = tid & 31, warp = tid >> 5;
    int g4 = lane >> 2, t4 = lane & 3;
    int qt = (gridDim.x - 1) - blockIdx.x;     // heavy tiles first
    int bh = blockIdx.y;
    int b = bh / HH, h = bh % HH;
    size_t base = (size_t)(b*SS)*D3 + h*HDIM;

    int qr0 = qt*64 + warp*16 + g4;
    int qr1 = qr0 + 8;

    // Q fragments (bf16, unscaled; 1/8 folded into logits)
    unsigned aq[4][4];
    const __nv_bfloat16* Qr0 = g_qkvb + base + (size_t)qr0*D3;
    const __nv_bfloat16* Qr1 = g_qkvb + base + (size_t)qr1*D3;
#pragma unroll
    for (int kb = 0; kb < 4; kb++) {
        aq[kb][0] = *(const unsigned*)&Qr0[kb*16 + 2*t4];
        aq[kb][1] = *(const unsigned*)&Qr1[kb*16 + 2*t4];
        aq[kb][2] = *(const unsigned*)&Qr0[kb*16 + 2*t4 + 8];
        aq[kb][3] = *(const unsigned*)&Qr1[kb*16 + 2*t4 + 8];
    }

    float m0 = -1e30f, m1 = -1e30f, l0 = 0.f, l1 = 0.f;
    float o[8][4] = {};
    int r0w = warp*16 + g4;      // local P row

    for (int kt = 0; kt <= qt; kt++) {
        __syncthreads();
#pragma unroll
        for (int l = 0; l < 4; l++) {
            int idx = tid + l*128;
            int r = idx >> 3, c8 = (idx & 7) * 8;
            size_t rowp = base + (size_t)(kt*64 + r)*D3;
            *(uint4*)&sK[r*72 + c8] = *(const uint4*)&g_qkvb[rowp + DD + c8];
            *(uint4*)&sV[r*72 + c8] = *(const uint4*)&g_qkvb[rowp + 2*DD + c8];
        }
        __syncthreads();

        // S = Q K^T
        float s[8][4] = {};
#pragma unroll
        for (int kb = 0; kb < 4; kb++) {
#pragma unroll
            for (int jt = 0; jt < 8; jt++) {
                unsigned b0 = sKw[(jt*8 + g4)*36 + kb*8 + t4];
                unsigned b1 = sKw[(jt*8 + g4)*36 + kb*8 + t4 + 4];
                mma_bf16(s[jt], aq[kb][0], aq[kb][1], aq[kb][2], aq[kb][3], b0, b1);
            }
        }
#pragma unroll
        for (int jt = 0; jt < 8; jt++)
#pragma unroll
            for (int c = 0; c < 4; c++) s[jt][c] *= 0.125f;

        if (kt == qt) {
            int lr0 = warp*16 + g4, lr1 = lr0 + 8;
#pragma unroll
            for (int jt = 0; jt < 8; jt++) {
                int c = jt*8 + t4*2;
                if (c     > lr0) s[jt][0] = -1e30f;
                if (c + 1 > lr0) s[jt][1] = -1e30f;
                if (c     > lr1) s[jt][2] = -1e30f;
                if (c + 1 > lr1) s[jt][3] = -1e30f;
            }
        }
        // online softmax (stats across thread-quad)
        float rm0 = -1e30f, rm1 = -1e30f;
#pragma unroll
        for (int jt = 0; jt < 8; jt++) {
            rm0 = fmaxf(rm0, fmaxf(s[jt][0], s[jt][1]));
            rm1 = fmaxf(rm1, fmaxf(s[jt][2], s[jt][3]));
        }
        rm0 = fmaxf(rm0, __shfl_xor_sync(0xffffffffu, rm0, 1));
        rm0 = fmaxf(rm0, __shfl_xor_sync(0xffffffffu, rm0, 2));
        rm1 = fmaxf(rm1, __shfl_xor_sync(0xffffffffu, rm1, 1));
        rm1 = fmaxf(rm1, __shfl_xor_sync(0xffffffffu, rm1, 2));
        float nm0 = fmaxf(m0, rm0), nm1 = fmaxf(m1, rm1);
        float sc0 = __expf(m0 - nm0), sc1 = __expf(m1 - nm1);
        float ps0 = 0.f, ps1 = 0.f;
#pragma unroll
        for (int jt = 0; jt < 8; jt++) {
            float p0 = __expf(s[jt][0] - nm0);
            float p1 = __expf(s[jt][1] - nm0);
            float p2 = __expf(s[jt][2] - nm1);
            float p3 = __expf(s[jt][3] - nm1);
            ps0 += p0 + p1; ps1 += p2 + p3;
            ((__nv_bfloat162*)sP)[r0w*36     + jt*4 + t4] = __floats2bfloat162_rn(p0, p1);
            ((__nv_bfloat162*)sP)[(r0w+8)*36 + jt*4 + t4] = __floats2bfloat162_rn(p2, p3);
        }
        ps0 += __shfl_xor_sync(0xffffffffu, ps0, 1);
        ps0 += __shfl_xor_sync(0xffffffffu, ps0, 2);
        ps1 += __shfl_xor_sync(0xffffffffu, ps1, 1);
        ps1 += __shfl_xor_sync(0xffffffffu, ps1, 2);
        l0 = l0*sc0 + ps0;  m0 = nm0;
        l1 = l1*sc1 + ps1;  m1 = nm1;
#pragma unroll
        for (int dt = 0; dt < 8; dt++) {
            o[dt][0] *= sc0; o[dt][1] *= sc0;
            o[dt][2] *= sc1; o[dt][3] *= sc1;
        }
        __syncwarp();   // sP rows are warp-private

        // O += P V
#pragma unroll
        for (int kb = 0; kb < 4; kb++) {
            unsigned ap0 = sPw[r0w*36     + kb*8 + t4];
            unsigned ap1 = sPw[(r0w+8)*36 + kb*8 + t4];
            unsigned ap2 = sPw[r0w*36     + kb*8 + t4 + 4];
            unsigned ap3 = sPw[(r0w+8)*36 + kb*8 + t4 + 4];
            int krow = kb*16 + 2*t4;
#pragma unroll
            for (int dt = 0; dt < 8; dt++) {
                int dcol = dt*8 + g4;
                unsigned b0 = (unsigned)sVh[krow*72 + dcol]
                            | ((unsigned)sVh[(krow+1)*72 + dcol] << 16);
                unsigned b1 = (unsigned)sVh[(krow+8)*72 + dcol]
                            | ((unsigned)sVh[(krow+9)*72 + dcol] << 16);
                mma_bf16(o[dt], ap0, ap1, ap2, ap3, b0, b1);
            }
        }
    }

    // write ctx (bf16)
    float inv0 = 1.0f / l0, inv1 = 1.0f / l1;
#pragma unroll
    for (int dt = 0; dt < 8; dt++) {
        int col = h*HDIM + dt*8 + t4*2;
        *(__nv_bfloat162*)&g_ctxb[(size_t)(b*SS + qr0)*DD + col] =
            __floats2bfloat162_rn(o[dt][0]*inv0, o[dt][1]*inv0);
        *(__nv_bfloat162*)&g_ctxb[(size_t)(b*SS + qr1)*DD + col] =
            __floats2bfloat162_rn(o[dt][2]*inv1, o[dt][3]*inv1);
    }
}

// ---------------- Router + top-2 (fp32 x2) ----------------
__global__ void router_kernel(const float* __restrict__ x2, const float* __restrict__ w_router) {
    int gid  = blockIdx.x*blockDim.x + threadIdx.x;
    int warp = gid >> 5;
    int lane = gid & 31;
    if (warp >= NTOK) return;
    float p[EE] = {};
    const float* xr = x2 + (size_t)warp*DD;
    for (int d = lane; d < DD; d += 32) {
        float xv = xr[d];
#pragma unroll
        for (int e = 0; e < EE; e++) p[e] += xv * w_router[e*DD + d];
    }
#pragma unroll
    for (int off = 16; off > 0; off >>= 1)
#pragma unroll
        for (int e = 0; e < EE; e++)
            p[e] += __shfl_down_sync(0xffffffffu, p[e], off);
    if (lane == 0) {
        float mx = p[0];
#pragma unroll
        for (int e = 1; e < EE; e++) mx = fmaxf(mx, p[e]);
        float ex[EE];
#pragma unroll
        for (int e = 0; e < EE; e++) ex[e] = expf(p[e] - mx);
        int i0 = 0;
#pragma unroll
        for (int e = 1; e < EE; e++) if (ex[e] > ex[i0]) i0 = e;
        int i1 = (i0 == 0) ? 1 : 0;
#pragma unroll
        for (int e = 0; e < EE; e++) if (e != i0 && ex[e] > ex[i1]) i1 = e;
        float denom = ex[i0] + ex[i1];
        g_topidx[warp*2+0] = i0;  g_topw[warp*2+0] = ex[i0]/denom;
        g_topidx[warp*2+1] = i1;  g_topw[warp*2+1] = ex[i1]/denom;
        atomicAdd(&g_counts[i0], 1);
        atomicAdd(&g_counts[i1], 1);
    }
}

__global__ void offsets_kernel() {
    g_offsets[0] = 0;
    for (int e = 0; e < EE; e++) {
        g_offsets[e+1] = g_offsets[e] + g_counts[e];
        g_cursor[e] = 0;
    }
}

__global__ void fill_kernel() {
    int t = blockIdx.x*blockDim.x + threadIdx.x;
    if (t >= NTOK) return;
#pragma unroll
    for (int k = 0; k < TOPK; k++) {
        int e = g_topidx[t*2+k];
        int pos = g_offsets[e] + atomicAdd(&g_cursor[e], 1);
        g_pairtok[pos] = t;
        g_pairw[pos]   = g_topw[t*2+k];
    }
}

// ---------------- launch ----------------
extern "C" void kernel_launch(void* const* d_in, const int* in_sizes, int n_in,
                              void* d_out, int out_size) {
    const float* hidden     = (const float*)d_in[0];
    const float* ln1_g      = (const float*)d_in[1];
    const float* ln1_b      = (const float*)d_in[2];
    const float* w_attn     = (const float*)d_in[3];
    const float* b_attn     = (const float*)d_in[4];
    const float* w_attnproj = (const float*)d_in[5];
    const float* b_attnproj = (const float*)d_in[6];
    const float* ln2_g      = (const float*)d_in[7];
    const float* ln2_b      = (const float*)d_in[8];
    const float* w_router   = (const float*)d_in[9];
    const float* w_fc       = (const float*)d_in[10];
    const float* b_fc       = (const float*)d_in[11];
    const float* w_proj     = (const float*)d_in[12];
    const float* b_proj     = (const float*)d_in[13];
    float* out = (float*)d_out;

    __nv_bfloat16 *xln1b, *qkvb, *ctxb, *x2b, *ghb;
    __nv_bfloat16 *wattnb, *waprojb, *wfcb, *wprojb;
    float *hs, *x2;
    int* counts;
    cudaGetSymbolAddress((void**)&xln1b,   g_xln1b);
    cudaGetSymbolAddress((void**)&qkvb,    g_qkvb);
    cudaGetSymbolAddress((void**)&ctxb,    g_ctxb);
    cudaGetSymbolAddress((void**)&hs,      g_hs);
    cudaGetSymbolAddress((void**)&x2,      g_x2);
    cudaGetSymbolAddress((void**)&x2b,     g_x2b);
    cudaGetSymbolAddress((void**)&ghb,     g_hb);
    cudaGetSymbolAddress((void**)&wattnb,  g_wattnb);
    cudaGetSymbolAddress((void**)&waprojb, g_waprojb);
    cudaGetSymbolAddress((void**)&wfcb,    g_wfcb);
    cudaGetSymbolAddress((void**)&wprojb,  g_wprojb);
    cudaGetSymbolAddress((void**)&counts,  g_counts);

    const int SM128 = 3*(128*40 + 32*136)*2;  // 56832
    const int SM64  = 3*(64*40  + 32*136)*2;  // 41472
    const int SMATT = 3*64*72*2;              // 27648

    cudaFuncSetAttribute((const void*)mma_gemm<0,128,128>, cudaFuncAttributeMaxDynamicSharedMemorySize, SM128);
    cudaFuncSetAttribute((const void*)mma_gemm<1,64,128>,  cudaFuncAttributeMaxDynamicSharedMemorySize, SM64);
    cudaFuncSetAttribute((const void*)mma_gemm<2,128,128>, cudaFuncAttributeMaxDynamicSharedMemorySize, SM128);
    cudaFuncSetAttribute((const void*)mma_gemm<3,128,128>, cudaFuncAttributeMaxDynamicSharedMemorySize, SM128);

    // weight conversions (bf16 caches); grid-stride, capped grid
    auto cvtgrid = [](int n4) { int g = (n4 + 255)/256; return g < 1184 ? g : 1184; };
    cvt_bf16<<<cvtgrid(DD*D3/4), 256>>>((const float4*)w_attn, (uint2*)wattnb, DD*D3/4);
    cvt_bf16<<<cvtgrid(DD*DD/4), 256>>>((const float4*)w_attnproj, (uint2*)waprojb, DD*DD/4);
    cvt_bf16<<<cvtgrid(EE*DD*FF/4), 256>>>((const float4*)w_fc, (uint2*)wfcb, EE*DD*FF/4);
    cvt_bf16<<<cvtgrid(EE*FF*DD/4), 256>>>((const float4*)w_proj, (uint2*)wprojb, EE*FF*DD/4);

    // attention sub-block
    ln_kernel<<<NTOK, 256>>>(hidden, ln1_g, ln1_b, nullptr, xln1b);
    mma_gemm<0,128,128><<<dim3(D3/128, NTOK/128, 1), 256, SM128>>>(
        xln1b, wattnb, b_attn, nullptr, qkvb, nullptr, NTOK, D3, DD);
    attn_mma<<<dim3(SS/64, BB*HH), 128, SMATT>>>();
    mma_gemm<1,64,128><<<dim3(DD/128, NTOK/64, 1), 256, SM64>>>(
        ctxb, waprojb, b_attnproj, hidden, hs, out, NTOK, DD, DD);

    // MoE sub-block
    ln_kernel<<<NTOK, 256>>>(hs, ln2_g, ln2_b, x2, x2b);
    cudaMemsetAsync(counts, 0, EE*sizeof(int));
    router_kernel<<<(NTOK*32)/256, 256>>>(x2, w_router);
    offsets_kernel<<<1,1>>>();
    fill_kernel<<<NTOK/256, 256>>>();
    mma_gemm<2,128,128><<<dim3(FF/128, NPAIR/128, EE), 256, SM128>>>(
        x2b, wfcb, b_fc, nullptr, ghb, nullptr, NPAIR, FF, DD);
    mma_gemm<3,128,128><<<dim3(DD/128, NPAIR/128, EE), 256, SM128>>>(
        ghb, wprojb, b_proj, nullptr, out, nullptr, NPAIR, DD, FF);
}

// round 12
// speedup vs baseline: 1.0625x; 1.0625x over previous
#include <cuda_runtime.h>
#include <cuda_bf16.h>
#include <math.h>

// Problem constants
#define BB 2
#define SS 1024
#define DD 768
#define HH 12
#define HDIM 64
#define EE 8
#define TOPK 2
#define FF 3072
#define NTOK (BB*SS)        // 2048
#define D3 (3*DD)           // 2304
#define NPAIR (NTOK*TOPK)   // 4096

// ---------------- device scratch ----------------
__device__ __nv_bfloat16 g_xln1b[NTOK*DD];
__device__ __nv_bfloat16 g_qkvb [NTOK*D3];
__device__ __nv_bfloat16 g_ctxb [NTOK*DD];
__device__ float         g_hs   [NTOK*DD];
__device__ float         g_x2   [NTOK*DD];
__device__ __nv_bfloat16 g_x2b  [NTOK*DD];
__device__ __nv_bfloat16 g_hb   [NPAIR*FF];
// bf16 weight caches (converted once per launch)
__device__ __nv_bfloat16 g_wattnb [DD*D3];
__device__ __nv_bfloat16 g_waprojb[DD*DD];
__device__ __nv_bfloat16 g_wfcb   [EE*DD*FF];
__device__ __nv_bfloat16 g_wprojb [EE*FF*DD];
__device__ int   g_topidx[NTOK*TOPK];
__device__ float g_topw [NTOK*TOPK];
__device__ int   g_counts[EE];
__device__ int   g_offsets[EE+1];
__device__ int   g_cursor[EE];
__device__ int   g_pairtok[NPAIR];
__device__ float g_pairw [NPAIR];

// ---------------- helpers ----------------
__device__ __forceinline__ void mma_bf16(float c[4], unsigned a0, unsigned a1,
                                         unsigned a2, unsigned a3,
                                         unsigned b0, unsigned b1) {
    asm volatile(
        "mma.sync.aligned.m16n8k16.row.col.f32.bf16.bf16.f32 "
        "{%0,%1,%2,%3},{%4,%5,%6,%7},{%8,%9},{%0,%1,%2,%3};"
        : "+f"(c[0]), "+f"(c[1]), "+f"(c[2]), "+f"(c[3])
        : "r"(a0), "r"(a1), "r"(a2), "r"(a3), "r"(b0), "r"(b1));
}
__device__ __forceinline__ void ldsm4(unsigned& r0, unsigned& r1, unsigned& r2,
                                      unsigned& r3, unsigned a) {
    asm volatile("ldmatrix.sync.aligned.m8n8.x4.shared.b16 {%0,%1,%2,%3},[%4];"
                 : "=r"(r0), "=r"(r1), "=r"(r2), "=r"(r3) : "r"(a));
}
__device__ __forceinline__ void ldsm4t(unsigned& r0, unsigned& r1, unsigned& r2,
                                       unsigned& r3, unsigned a) {
    asm volatile("ldmatrix.sync.aligned.m8n8.x4.trans.shared.b16 {%0,%1,%2,%3},[%4];"
                 : "=r"(r0), "=r"(r1), "=r"(r2), "=r"(r3) : "r"(a));
}
__device__ __forceinline__ void cp16(void* smem_dst, const void* gsrc, bool valid) {
    unsigned dst = (unsigned)__cvta_generic_to_shared(smem_dst);
    int sz = valid ? 16 : 0;
    asm volatile("cp.async.cg.shared.global [%0], [%1], 16, %2;"
                 :: "r"(dst), "l"(gsrc), "r"(sz));
}
__device__ __forceinline__ void cp_commit() {
    asm volatile("cp.async.commit_group;");
}
__device__ __forceinline__ void cp_wait0() {
    asm volatile("cp.async.wait_group 0;" ::: "memory");
}
__device__ __forceinline__ void cp_wait1() {
    asm volatile("cp.async.wait_group 1;" ::: "memory");
}

// ---------------- fp32 -> bf16 weight conversion (grid-stride, MLP 4) ----------------
__global__ void cvt_bf16(const float4* __restrict__ src, uint2* __restrict__ dst, int n4) {
    int stride = gridDim.x * blockDim.x;
#pragma unroll 4
    for (int i = blockIdx.x*blockDim.x + threadIdx.x; i < n4; i += stride) {
        float4 a = src[i];
        __nv_bfloat162 h0 = __floats2bfloat162_rn(a.x, a.y);
        __nv_bfloat162 h1 = __floats2bfloat162_rn(a.z, a.w);
        dst[i] = make_uint2(*(unsigned*)&h0, *(unsigned*)&h1);
    }
}

// ---------------- LayerNorm (fp32 in; optional fp32 out + bf16 out) ----------------
__global__ void ln_kernel(const float* __restrict__ x,
                          const float* __restrict__ g,
                          const float* __restrict__ b,
                          float* __restrict__ outf,
                          __nv_bfloat16* __restrict__ outb) {
    int row = blockIdx.x;
    int tid = threadIdx.x;
    const float* xr = x + (size_t)row*DD;
    float v[3];
    float s = 0.f, s2 = 0.f;
#pragma unroll
    for (int i = 0; i < 3; i++) {
        v[i] = xr[tid + i*256];
        s += v[i]; s2 += v[i]*v[i];
    }
    __shared__ float2 red[256];
    red[tid] = make_float2(s, s2);
    __syncthreads();
    for (int off = 128; off > 0; off >>= 1) {
        if (tid < off) {
            red[tid].x += red[tid+off].x;
            red[tid].y += red[tid+off].y;
        }
        __syncthreads();
    }
    float mu  = red[0].x * (1.0f/DD);
    float var = red[0].y * (1.0f/DD) - mu*mu;
    float inv = rsqrtf(var + 1e-5f);
#pragma unroll
    for (int i = 0; i < 3; i++) {
        int c = tid + i*256;
        float val = (v[i] - mu) * inv * g[c] + b[c];
        if (outf) outf[(size_t)row*DD + c] = val;
        outb[(size_t)row*DD + c] = __float2bfloat16(val);
    }
}

// ---------------- bf16 MMA GEMM: k-step 32, ldmatrix frags, 3-stage cp.async --------
// MODE 0: Cb = bf16(A@B + bias)                  (QKV)
// MODE 1: C = A@B + bias + resid; C2 = C (fp32)  (attn out proj + out init)
// MODE 2: Cb = bf16(gelu(gather(A)@B[e]+bias))   (MoE FC)
// MODE 3: atomic C[tok] += w*(A@B[e]+bias[e])    (MoE PROJ)
template<int MODE, int TM, int TN>
__global__ void __launch_bounds__(256)
mma_gemm(const __nv_bfloat16* __restrict__ A, const __nv_bfloat16* __restrict__ B,
         const float* __restrict__ bias, const float* __restrict__ resid,
         void* __restrict__ Cv, float* __restrict__ C2, int M, int N, int K) {
    constexpr int MI = TM/32;          // m16 tiles per warp
    constexpr int NI = TN/32;          // n8 tiles per warp
    constexpr int WCOL = TN/4;         // warp col span
    constexpr int APAD = 40;           // bf16 per A row (80B: odd 16B units)
    constexpr int BPAD = TN + 8;       // bf16 per B row (odd 16B units)
    constexpr int ASTRIDE = TM*APAD;
    constexpr int BSTRIDE = 32*BPAD;
    constexpr int ACT = TM*4/256;      // A 16B chunks per thread per stage
    constexpr int BCT = TN*4/256;      // B 16B chunks per thread per stage

    int e = 0, seg = 0, cnt = M;
    if (MODE >= 2) {
        e = blockIdx.z;
        seg = g_offsets[e];
        cnt = g_offsets[e+1] - seg;
    }
    int rowBase = blockIdx.y * TM;
    if (rowBase >= cnt) return;
    int colBase = blockIdx.x * TN;
    const __nv_bfloat16* Bm = B + (size_t)e*K*N;
    const float* biasv = bias + (size_t)e*N;

    extern __shared__ __nv_bfloat16 smemb[];
    __nv_bfloat16* Asm = smemb;                 // 3 stages [TM][APAD]
    __nv_bfloat16* Bsm = smemb + 3*ASTRIDE;     // 3 stages [32][BPAD]
    __shared__ int sTok[TM];

    int tid = threadIdx.x;
    int lane = tid & 31, warp = tid >> 5;
    int wy = warp >> 2, wx = warp & 3;
    int g4 = lane >> 2, t4 = lane & 3;

    if (MODE == 2) {
        for (int i = tid; i < TM; i += 256)
            sTok[i] = (rowBase + i < cnt) ? g_pairtok[seg + rowBase + i] : -1;
        __syncthreads();
    }

    // A chunk coords
    int arow[ACT], akh[ACT];
    const __nv_bfloat16* aptr[ACT];
    bool avalid[ACT];
#pragma unroll
    for (int l = 0; l < ACT; l++) {
        int idx = tid + l*256;
        arow[l] = idx >> 2; akh[l] = (idx & 3) * 8;
        if (MODE == 2) {
            int tk = sTok[arow[l]];
            avalid[l] = (tk >= 0);
            aptr[l] = A + (avalid[l] ? (size_t)tk*K : 0) + akh[l];
        } else if (MODE == 3) {
            avalid[l] = (rowBase + arow[l] < cnt);
            aptr[l] = A + (avalid[l] ? (size_t)(seg + rowBase + arow[l])*K : 0) + akh[l];
        } else {
            avalid[l] = true;
            aptr[l] = A + (size_t)(rowBase + arow[l])*K + akh[l];
        }
    }
    // B chunk coords: 32 rows x TN cols bf16
    int brow[BCT], bseg[BCT];
    const __nv_bfloat16* bptr[BCT];
#pragma unroll
    for (int l = 0; l < BCT; l++) {
        int idx = tid + l*256;
        brow[l] = idx / (TN/8); bseg[l] = (idx % (TN/8)) * 8;
        bptr[l] = Bm + (size_t)brow[l]*N + colBase + bseg[l];
    }

    float acc[MI][NI][4] = {};
    int nt = K / 32;

    // prologue: tiles 0 and 1
#pragma unroll
    for (int p = 0; p < 2; p++) {
        int k0 = p * 32;
#pragma unroll
        for (int l = 0; l < ACT; l++)
            cp16(&Asm[p*ASTRIDE + arow[l]*APAD + akh[l]], aptr[l] + k0, avalid[l]);
#pragma unroll
        for (int l = 0; l < BCT; l++)
            cp16(&Bsm[p*BSTRIDE + brow[l]*BPAD + bseg[l]], bptr[l] + (size_t)k0*N, true);
        cp_commit();
    }

    // ldmatrix lane addressing
    int lrow = lane & 15;
    int lcol = (lane >> 4) * 8;

    for (int kt = 0; kt < nt; kt++) {
        if (kt + 1 < nt) cp_wait1(); else cp_wait0();
        __syncthreads();
        if (kt + 2 < nt) {
            int st = (kt + 2) % 3;
            int k0 = (kt + 2) * 32;
#pragma unroll
            for (int l = 0; l < ACT; l++)
                cp16(&Asm[st*ASTRIDE + arow[l]*APAD + akh[l]], aptr[l] + k0, avalid[l]);
#pragma unroll
            for (int l = 0; l < BCT; l++)
                cp16(&Bsm[st*BSTRIDE + brow[l]*BPAD + bseg[l]], bptr[l] + (size_t)k0*N, true);
            cp_commit();
        }
        unsigned abase = (unsigned)__cvta_generic_to_shared(Asm + (kt % 3)*ASTRIDE);
        unsigned bbase = (unsigned)__cvta_generic_to_shared(Bsm + (kt % 3)*BSTRIDE);

#pragma unroll
        for (int ks = 0; ks < 32; ks += 16) {
            unsigned af[MI][4];
#pragma unroll
            for (int mi = 0; mi < MI; mi++) {
                unsigned addr = abase + ((wy*(TM/2) + mi*16 + lrow)*APAD + ks + lcol)*2;
                ldsm4(af[mi][0], af[mi][1], af[mi][2], af[mi][3], addr);
            }
            unsigned bf[NI][2];
#pragma unroll
            for (int nh = 0; nh < NI/2; nh++) {
                unsigned addr = bbase + ((ks + lrow)*BPAD + wx*WCOL + nh*16 + lcol)*2;
                ldsm4t(bf[nh*2][0], bf[nh*2][1], bf[nh*2+1][0], bf[nh*2+1][1], addr);
            }
#pragma unroll
            for (int mi = 0; mi < MI; mi++)
#pragma unroll
                for (int ni = 0; ni < NI; ni++)
                    mma_bf16(acc[mi][ni], af[mi][0], af[mi][1], af[mi][2], af[mi][3],
                             bf[ni][0], bf[ni][1]);
        }
    }

    // epilogue
    __nv_bfloat16* Cb = (__nv_bfloat16*)Cv;
    float* C = (float*)Cv;
#pragma unroll
    for (int mi = 0; mi < MI; mi++) {
#pragma unroll
        for (int ci = 0; ci < 2; ci++) {
            int r = wy*(TM/2) + mi*16 + g4 + ci*8;
            int grow = rowBase + r;
            if (grow >= cnt) continue;
#pragma unroll
            for (int ni = 0; ni < NI; ni++) {
                int col = colBase + wx*WCOL + ni*8 + t4*2;
                float v0 = acc[mi][ni][ci*2 + 0];
                float v1 = acc[mi][ni][ci*2 + 1];
                if (MODE == 0) {
                    v0 += biasv[col]; v1 += biasv[col+1];
                    *(__nv_bfloat162*)&Cb[(size_t)grow*N + col] = __floats2bfloat162_rn(v0, v1);
                } else if (MODE == 1) {
                    const float2 rr = *(const float2*)&resid[(size_t)grow*N + col];
                    v0 += biasv[col]   + rr.x;
                    v1 += biasv[col+1] + rr.y;
                    *(float2*)&C [(size_t)grow*N + col] = make_float2(v0, v1);
                    *(float2*)&C2[(size_t)grow*N + col] = make_float2(v0, v1);
                } else if (MODE == 2) {
                    v0 += biasv[col]; v1 += biasv[col+1];
                    v0 = 0.5f*v0*(1.0f + erff(v0*0.70710678118654752f));
                    v1 = 0.5f*v1*(1.0f + erff(v1*0.70710678118654752f));
                    *(__nv_bfloat162*)&Cb[(size_t)(seg + grow)*N + col] = __floats2bfloat162_rn(v0, v1);
                } else {
                    int p = seg + grow;
                    int tok = g_pairtok[p];
                    float pw = g_pairw[p];
                    atomicAdd(&C[(size_t)tok*N + col],   pw*(v0 + biasv[col]));
                    atomicAdd(&C[(size_t)tok*N + col+1], pw*(v1 + biasv[col+1]));
                }
            }
        }
    }
}

// ---------------- bf16 tensor-core attention (single-buffer, R8 form) ----------------
// 128 threads = 4 warps; warp owns 16 query rows. smem K/V/P tiles [64][72] bf16.
__global__ void __launch_bounds__(128) attn_mma() {
    extern __shared__ __nv_bfloat16 sm16[];
    __nv_bfloat16* sK = sm16;             // [64][72]
    __nv_bfloat16* sV = sm16 + 64*72;     // [64][72]
    __nv_bfloat16* sP = sm16 + 2*64*72;   // [64][72]
    const unsigned* sKw = (const unsigned*)sK;
    const unsigned* sPw = (const unsigned*)sP;
    const unsigned short* sVh = (const unsigned short*)sV;

    int tid = threadIdx.x;
    int lane = tid & 31, warp = tid >> 5;
    int g4 = lane >> 2, t4 = lane & 3;
    int qt = (gridDim.x - 1) - blockIdx.x;     // heavy tiles first
    int bh = blockIdx.y;
    int b = bh / HH, h = bh % HH;
    size_t base = (size_t)(b*SS)*D3 + h*HDIM;

    int qr0 = qt*64 + warp*16 + g4;
    int qr1 = qr0 + 8;

    // Q fragments (bf16, unscaled; 1/8 folded into logits)
    unsigned aq[4][4];
    const __nv_bfloat16* Qr0 = g_qkvb + base + (size_t)qr0*D3;
    const __nv_bfloat16* Qr1 = g_qkvb + base + (size_t)qr1*D3;
#pragma unroll
    for (int kb = 0; kb < 4; kb++) {
        aq[kb][0] = *(const unsigned*)&Qr0[kb*16 + 2*t4];
        aq[kb][1] = *(const unsigned*)&Qr1[kb*16 + 2*t4];
        aq[kb][2] = *(const unsigned*)&Qr0[kb*16 + 2*t4 + 8];
        aq[kb][3] = *(const unsigned*)&Qr1[kb*16 + 2*t4 + 8];
    }

    float m0 = -1e30f, m1 = -1e30f, l0 = 0.f, l1 = 0.f;
    float o[8][4] = {};
    int r0w = warp*16 + g4;      // local P row

    for (int kt = 0; kt <= qt; kt++) {
        __syncthreads();
#pragma unroll
        for (int l = 0; l < 4; l++) {
            int idx = tid + l*128;
            int r = idx >> 3, c8 = (idx & 7) * 8;
            size_t rowp = base + (size_t)(kt*64 + r)*D3;
            *(uint4*)&sK[r*72 + c8] = *(const uint4*)&g_qkvb[rowp + DD + c8];
            *(uint4*)&sV[r*72 + c8] = *(const uint4*)&g_qkvb[rowp + 2*DD + c8];
        }
        __syncthreads();

        // S = Q K^T
        float s[8][4] = {};
#pragma unroll
        for (int kb = 0; kb < 4; kb++) {
#pragma unroll
            for (int jt = 0; jt < 8; jt++) {
                unsigned b0 = sKw[(jt*8 + g4)*36 + kb*8 + t4];
                unsigned b1 = sKw[(jt*8 + g4)*36 + kb*8 + t4 + 4];
                mma_bf16(s[jt], aq[kb][0], aq[kb][1], aq[kb][2], aq[kb][3], b0, b1);
            }
        }
#pragma unroll
        for (int jt = 0; jt < 8; jt++)
#pragma unroll
            for (int c = 0; c < 4; c++) s[jt][c] *= 0.125f;

        if (kt == qt) {
            int lr0 = warp*16 + g4, lr1 = lr0 + 8;
#pragma unroll
            for (int jt = 0; jt < 8; jt++) {
                int c = jt*8 + t4*2;
                if (c     > lr0) s[jt][0] = -1e30f;
                if (c + 1 > lr0) s[jt][1] = -1e30f;
                if (c     > lr1) s[jt][2] = -1e30f;
                if (c + 1 > lr1) s[jt][3] = -1e30f;
            }
        }
        // online softmax (stats across thread-quad)
        float rm0 = -1e30f, rm1 = -1e30f;
#pragma unroll
        for (int jt = 0; jt < 8; jt++) {
            rm0 = fmaxf(rm0, fmaxf(s[jt][0], s[jt][1]));
            rm1 = fmaxf(rm1, fmaxf(s[jt][2], s[jt][3]));
        }
        rm0 = fmaxf(rm0, __shfl_xor_sync(0xffffffffu, rm0, 1));
        rm0 = fmaxf(rm0, __shfl_xor_sync(0xffffffffu, rm0, 2));
        rm1 = fmaxf(rm1, __shfl_xor_sync(0xffffffffu, rm1, 1));
        rm1 = fmaxf(rm1, __shfl_xor_sync(0xffffffffu, rm1, 2));
        float nm0 = fmaxf(m0, rm0), nm1 = fmaxf(m1, rm1);
        float sc0 = __expf(m0 - nm0), sc1 = __expf(m1 - nm1);
        float ps0 = 0.f, ps1 = 0.f;
#pragma unroll
        for (int jt = 0; jt < 8; jt++) {
            float p0 = __expf(s[jt][0] - nm0);
            float p1 = __expf(s[jt][1] - nm0);
            float p2 = __expf(s[jt][2] - nm1);
            float p3 = __expf(s[jt][3] - nm1);
            ps0 += p0 + p1; ps1 += p2 + p3;
            ((__nv_bfloat162*)sP)[r0w*36     + jt*4 + t4] = __floats2bfloat162_rn(p0, p1);
            ((__nv_bfloat162*)sP)[(r0w+8)*36 + jt*4 + t4] = __floats2bfloat162_rn(p2, p3);
        }
        ps0 += __shfl_xor_sync(0xffffffffu, ps0, 1);
        ps0 += __shfl_xor_sync(0xffffffffu, ps0, 2);
        ps1 += __shfl_xor_sync(0xffffffffu, ps1, 1);
        ps1 += __shfl_xor_sync(0xffffffffu, ps1, 2);
        l0 = l0*sc0 + ps0;  m0 = nm0;
        l1 = l1*sc1 + ps1;  m1 = nm1;
#pragma unroll
        for (int dt = 0; dt < 8; dt++) {
            o[dt][0] *= sc0; o[dt][1] *= sc0;
            o[dt][2] *= sc1; o[dt][3] *= sc1;
        }
        __syncwarp();   // sP rows are warp-private

        // O += P V
#pragma unroll
        for (int kb = 0; kb < 4; kb++) {
            unsigned ap0 = sPw[r0w*36     + kb*8 + t4];
            unsigned ap1 = sPw[(r0w+8)*36 + kb*8 + t4];
            unsigned ap2 = sPw[r0w*36     + kb*8 + t4 + 4];
            unsigned ap3 = sPw[(r0w+8)*36 + kb*8 + t4 + 4];
            int krow = kb*16 + 2*t4;
#pragma unroll
            for (int dt = 0; dt < 8; dt++) {
                int dcol = dt*8 + g4;
                unsigned b0 = (unsigned)sVh[krow*72 + dcol]
                            | ((unsigned)sVh[(krow+1)*72 + dcol] << 16);
                unsigned b1 = (unsigned)sVh[(krow+8)*72 + dcol]
                            | ((unsigned)sVh[(krow+9)*72 + dcol] << 16);
                mma_bf16(o[dt], ap0, ap1, ap2, ap3, b0, b1);
            }
        }
    }

    // write ctx (bf16)
    float inv0 = 1.0f / l0, inv1 = 1.0f / l1;
#pragma unroll
    for (int dt = 0; dt < 8; dt++) {
        int col = h*HDIM + dt*8 + t4*2;
        *(__nv_bfloat162*)&g_ctxb[(size_t)(b*SS + qr0)*DD + col] =
            __floats2bfloat162_rn(o[dt][0]*inv0, o[dt][1]*inv0);
        *(__nv_bfloat162*)&g_ctxb[(size_t)(b*SS + qr1)*DD + col] =
            __floats2bfloat162_rn(o[dt][2]*inv1, o[dt][3]*inv1);
    }
}

// ---------------- Router + top-2 (fp32 x2) ----------------
__global__ void router_kernel(const float* __restrict__ x2, const float* __restrict__ w_router) {
    int gid  = blockIdx.x*blockDim.x + threadIdx.x;
    int warp = gid >> 5;
    int lane = gid & 31;
    if (warp >= NTOK) return;
    float p[EE] = {};
    const float* xr = x2 + (size_t)warp*DD;
    for (int d = lane; d < DD; d += 32) {
        float xv = xr[d];
#pragma unroll
        for (int e = 0; e < EE; e++) p[e] += xv * w_router[e*DD + d];
    }
#pragma unroll
    for (int off = 16; off > 0; off >>= 1)
#pragma unroll
        for (int e = 0; e < EE; e++)
            p[e] += __shfl_down_sync(0xffffffffu, p[e], off);
    if (lane == 0) {
        float mx = p[0];
#pragma unroll
        for (int e = 1; e < EE; e++) mx = fmaxf(mx, p[e]);
        float ex[EE];
#pragma unroll
        for (int e = 0; e < EE; e++) ex[e] = expf(p[e] - mx);
        int i0 = 0;
#pragma unroll
        for (int e = 1; e < EE; e++) if (ex[e] > ex[i0]) i0 = e;
        int i1 = (i0 == 0) ? 1 : 0;
#pragma unroll
        for (int e = 0; e < EE; e++) if (e != i0 && ex[e] > ex[i1]) i1 = e;
        float denom = ex[i0] + ex[i1];
        g_topidx[warp*2+0] = i0;  g_topw[warp*2+0] = ex[i0]/denom;
        g_topidx[warp*2+1] = i1;  g_topw[warp*2+1] = ex[i1]/denom;
        atomicAdd(&g_counts[i0], 1);
        atomicAdd(&g_counts[i1], 1);
    }
}

// ---------------- fused offsets + scatter (one block) ----------------
__global__ void scatter_kernel() {
    int tid = threadIdx.x;
    if (tid == 0) {
        g_offsets[0] = 0;
        for (int e = 0; e < EE; e++) {
            g_offsets[e+1] = g_offsets[e] + g_counts[e];
            g_cursor[e] = 0;
        }
    }
    __syncthreads();
    for (int t = tid; t < NTOK; t += blockDim.x) {
#pragma unroll
        for (int k = 0; k < TOPK; k++) {
            int e = g_topidx[t*2+k];
            int pos = g_offsets[e] + atomicAdd(&g_cursor[e], 1);
            g_pairtok[pos] = t;
            g_pairw[pos]   = g_topw[t*2+k];
        }
    }
}

// ---------------- launch ----------------
extern "C" void kernel_launch(void* const* d_in, const int* in_sizes, int n_in,
                              void* d_out, int out_size) {
    const float* hidden     = (const float*)d_in[0];
    const float* ln1_g      = (const float*)d_in[1];
    const float* ln1_b      = (const float*)d_in[2];
    const float* w_attn     = (const float*)d_in[3];
    const float* b_attn     = (const float*)d_in[4];
    const float* w_attnproj = (const float*)d_in[5];
    const float* b_attnproj = (const float*)d_in[6];
    const float* ln2_g      = (const float*)d_in[7];
    const float* ln2_b      = (const float*)d_in[8];
    const float* w_router   = (const float*)d_in[9];
    const float* w_fc       = (const float*)d_in[10];
    const float* b_fc       = (const float*)d_in[11];
    const float* w_proj     = (const float*)d_in[12];
    const float* b_proj     = (const float*)d_in[13];
    float* out = (float*)d_out;

    __nv_bfloat16 *xln1b, *qkvb, *ctxb, *x2b, *ghb;
    __nv_bfloat16 *wattnb, *waprojb, *wfcb, *wprojb;
    float *hs, *x2;
    int* counts;
    cudaGetSymbolAddress((void**)&xln1b,   g_xln1b);
    cudaGetSymbolAddress((void**)&qkvb,    g_qkvb);
    cudaGetSymbolAddress((void**)&ctxb,    g_ctxb);
    cudaGetSymbolAddress((void**)&hs,      g_hs);
    cudaGetSymbolAddress((void**)&x2,      g_x2);
    cudaGetSymbolAddress((void**)&x2b,     g_x2b);
    cudaGetSymbolAddress((void**)&ghb,     g_hb);
    cudaGetSymbolAddress((void**)&wattnb,  g_wattnb);
    cudaGetSymbolAddress((void**)&waprojb, g_waprojb);
    cudaGetSymbolAddress((void**)&wfcb,    g_wfcb);
    cudaGetSymbolAddress((void**)&wprojb,  g_wprojb);
    cudaGetSymbolAddress((void**)&counts,  g_counts);

    const int SM128 = 3*(128*40 + 32*136)*2;  // 56832
    const int SM64  = 3*(64*40  + 32*136)*2;  // 41472
    const int SMATT = 3*64*72*2;              // 27648

    cudaFuncSetAttribute((const void*)mma_gemm<0,128,128>, cudaFuncAttributeMaxDynamicSharedMemorySize, SM128);
    cudaFuncSetAttribute((const void*)mma_gemm<1,64,128>,  cudaFuncAttributeMaxDynamicSharedMemorySize, SM64);
    cudaFuncSetAttribute((const void*)mma_gemm<2,128,128>, cudaFuncAttributeMaxDynamicSharedMemorySize, SM128);
    cudaFuncSetAttribute((const void*)mma_gemm<3,64,128>,  cudaFuncAttributeMaxDynamicSharedMemorySize, SM64);

    // side stream + events (created once; per-call work is identical)
    static cudaStream_t s2 = nullptr;
    static cudaEvent_t evFork = nullptr, evJoin = nullptr;
    if (!s2) {
        cudaStreamCreateWithFlags(&s2, cudaStreamNonBlocking);
        cudaEventCreateWithFlags(&evFork, cudaEventDisableTiming);
        cudaEventCreateWithFlags(&evJoin, cudaEventDisableTiming);
    }

    auto cvtgrid = [](int n4) { int g = (n4 + 255)/256; return g < 1184 ? g : 1184; };

    // fork: big MoE weight conversions run on s2, overlapped with attention phase
    cudaEventRecord(evFork, 0);
    cudaStreamWaitEvent(s2, evFork, 0);
    cvt_bf16<<<cvtgrid(EE*DD*FF/4), 256, 0, s2>>>((const float4*)w_fc, (uint2*)wfcb, EE*DD*FF/4);
    cvt_bf16<<<cvtgrid(EE*FF*DD/4), 256, 0, s2>>>((const float4*)w_proj, (uint2*)wprojb, EE*FF*DD/4);
    cudaEventRecord(evJoin, s2);

    // main stream: small conversions + attention sub-block
    cvt_bf16<<<cvtgrid(DD*D3/4), 256>>>((const float4*)w_attn, (uint2*)wattnb, DD*D3/4);
    cvt_bf16<<<cvtgrid(DD*DD/4), 256>>>((const float4*)w_attnproj, (uint2*)waprojb, DD*DD/4);
    ln_kernel<<<NTOK, 256>>>(hidden, ln1_g, ln1_b, nullptr, xln1b);
    mma_gemm<0,128,128><<<dim3(D3/128, NTOK/128, 1), 256, SM128>>>(
        xln1b, wattnb, b_attn, nullptr, qkvb, nullptr, NTOK, D3, DD);
    attn_mma<<<dim3(SS/64, BB*HH), 128, SMATT>>>();
    mma_gemm<1,64,128><<<dim3(DD/128, NTOK/64, 1), 256, SM64>>>(
        ctxb, waprojb, b_attnproj, hidden, hs, out, NTOK, DD, DD);

    // MoE routing
    ln_kernel<<<NTOK, 256>>>(hs, ln2_g, ln2_b, x2, x2b);
    cudaMemsetAsync(counts, 0, EE*sizeof(int));
    router_kernel<<<(NTOK*32)/256, 256>>>(x2, w_router);
    scatter_kernel<<<1, 256>>>();

    // join: FC/PROJ need the converted MoE weights
    cudaStreamWaitEvent(0, evJoin, 0);
    mma_gemm<2,128,128><<<dim3(FF/128, NPAIR/128, EE), 256, SM128>>>(
        x2b, wfcb, b_fc, nullptr, ghb, nullptr, NPAIR, FF, DD);
    mma_gemm<3,64,128><<<dim3(DD/128, NPAIR/64, EE), 256, SM64>>>(
        ghb, wprojb, b_proj, nullptr, out, nullptr, NPAIR, DD, FF);
}

// round 15
// speedup vs baseline: 1.1166x; 1.0509x over previous
#include <cuda_runtime.h>
#include <cuda_bf16.h>
#include <math.h>

// Problem constants
#define BB 2
#define SS 1024
#define DD 768
#define HH 12
#define HDIM 64
#define EE 8
#define TOPK 2
#define FF 3072
#define NTOK (BB*SS)        // 2048
#define D3 (3*DD)           // 2304
#define NPAIR (NTOK*TOPK)   // 4096

// ---------------- device scratch ----------------
__device__ __nv_bfloat16 g_xln1b[NTOK*DD];
__device__ __nv_bfloat16 g_qkvb [NTOK*D3];
__device__ __nv_bfloat16 g_ctxb [NTOK*DD];
__device__ float         g_hs   [NTOK*DD];
__device__ __nv_bfloat16 g_x2b  [NTOK*DD];
__device__ __nv_bfloat16 g_hb   [NPAIR*FF];
// bf16 weight caches (converted once per launch)
__device__ __nv_bfloat16 g_wattnb [DD*D3];
__device__ __nv_bfloat16 g_waprojb[DD*DD];
__device__ __nv_bfloat16 g_wfcb   [EE*DD*FF];
__device__ __nv_bfloat16 g_wprojb [EE*FF*DD];
__device__ int   g_topidx[NTOK*TOPK];
__device__ float g_topw [NTOK*TOPK];
__device__ int   g_counts[EE];
__device__ int   g_offsets[EE+1];
__device__ int   g_cursor[EE];
__device__ int   g_pairtok[NPAIR];
__device__ float g_pairw [NPAIR];

// ---------------- helpers ----------------
__device__ __forceinline__ unsigned packbf(float x, float y) {
    __nv_bfloat162 h = __floats2bfloat162_rn(x, y);
    return *(unsigned*)&h;
}
__device__ __forceinline__ void mma_bf16(float c[4], unsigned a0, unsigned a1,
                                         unsigned a2, unsigned a3,
                                         unsigned b0, unsigned b1) {
    asm volatile(
        "mma.sync.aligned.m16n8k16.row.col.f32.bf16.bf16.f32 "
        "{%0,%1,%2,%3},{%4,%5,%6,%7},{%8,%9},{%0,%1,%2,%3};"
        : "+f"(c[0]), "+f"(c[1]), "+f"(c[2]), "+f"(c[3])
        : "r"(a0), "r"(a1), "r"(a2), "r"(a3), "r"(b0), "r"(b1));
}
__device__ __forceinline__ void ldsm4(unsigned& r0, unsigned& r1, unsigned& r2,
                                      unsigned& r3, unsigned a) {
    asm volatile("ldmatrix.sync.aligned.m8n8.x4.shared.b16 {%0,%1,%2,%3},[%4];"
                 : "=r"(r0), "=r"(r1), "=r"(r2), "=r"(r3) : "r"(a));
}
__device__ __forceinline__ void ldsm4t(unsigned& r0, unsigned& r1, unsigned& r2,
                                       unsigned& r3, unsigned a) {
    asm volatile("ldmatrix.sync.aligned.m8n8.x4.trans.shared.b16 {%0,%1,%2,%3},[%4];"
                 : "=r"(r0), "=r"(r1), "=r"(r2), "=r"(r3) : "r"(a));
}
__device__ __forceinline__ void cp16(void* smem_dst, const void* gsrc, bool valid) {
    unsigned dst = (unsigned)__cvta_generic_to_shared(smem_dst);
    int sz = valid ? 16 : 0;
    asm volatile("cp.async.cg.shared.global [%0], [%1], 16, %2;"
                 :: "r"(dst), "l"(gsrc), "r"(sz));
}
__device__ __forceinline__ void cp_commit() {
    asm volatile("cp.async.commit_group;");
}
__device__ __forceinline__ void cp_wait0() {
    asm volatile("cp.async.wait_group 0;" ::: "memory");
}
__device__ __forceinline__ void cp_wait1() {
    asm volatile("cp.async.wait_group 1;" ::: "memory");
}

// ---------------- fp32 -> bf16 weight conversion (grid-stride, MLP 4) ----------------
__global__ void cvt_bf16(const float4* __restrict__ src, uint2* __restrict__ dst, int n4) {
    int stride = gridDim.x * blockDim.x;
#pragma unroll 4
    for (int i = blockIdx.x*blockDim.x + threadIdx.x; i < n4; i += stride) {
        float4 a = src[i];
        __nv_bfloat162 h0 = __floats2bfloat162_rn(a.x, a.y);
        __nv_bfloat162 h1 = __floats2bfloat162_rn(a.z, a.w);
        dst[i] = make_uint2(*(unsigned*)&h0, *(unsigned*)&h1);
    }
}

// ---------------- LayerNorm 1 (fp32 in, bf16 out) ----------------
__global__ void ln_kernel(const float* __restrict__ x,
                          const float* __restrict__ g,
                          const float* __restrict__ b,
                          __nv_bfloat16* __restrict__ outb) {
    int row = blockIdx.x;
    int tid = threadIdx.x;
    const float* xr = x + (size_t)row*DD;
    float v[3];
    float s = 0.f, s2 = 0.f;
#pragma unroll
    for (int i = 0; i < 3; i++) {
        v[i] = xr[tid + i*256];
        s += v[i]; s2 += v[i]*v[i];
    }
    __shared__ float2 red[256];
    red[tid] = make_float2(s, s2);
    __syncthreads();
    for (int off = 128; off > 0; off >>= 1) {
        if (tid < off) {
            red[tid].x += red[tid+off].x;
            red[tid].y += red[tid+off].y;
        }
        __syncthreads();
    }
    float mu  = red[0].x * (1.0f/DD);
    float var = red[0].y * (1.0f/DD) - mu*mu;
    float inv = rsqrtf(var + 1e-5f);
#pragma unroll
    for (int i = 0; i < 3; i++) {
        int c = tid + i*256;
        outb[(size_t)row*DD + c] = __float2bfloat16((v[i] - mu) * inv * g[c] + b[c]);
    }
}

// ---------------- LayerNorm 2 + router fused (one block per token) ----------------
__global__ void ln2_router_kernel(const float* __restrict__ x,
                                  const float* __restrict__ g,
                                  const float* __restrict__ b,
                                  __nv_bfloat16* __restrict__ outb,
                                  const float* __restrict__ w_router) {
    int row = blockIdx.x;
    int tid = threadIdx.x;
    int warp = tid >> 5, lane = tid & 31;
    const float* xr = x + (size_t)row*DD;
    float v[3];
    float s = 0.f, s2 = 0.f;
#pragma unroll
    for (int i = 0; i < 3; i++) {
        v[i] = xr[tid + i*256];
        s += v[i]; s2 += v[i]*v[i];
    }
    __shared__ float2 red[256];
    __shared__ float sx[DD];
    __shared__ float slog[EE];
    red[tid] = make_float2(s, s2);
    __syncthreads();
    for (int off = 128; off > 0; off >>= 1) {
        if (tid < off) {
            red[tid].x += red[tid+off].x;
            red[tid].y += red[tid+off].y;
        }
        __syncthreads();
    }
    float mu  = red[0].x * (1.0f/DD);
    float var = red[0].y * (1.0f/DD) - mu*mu;
    float inv = rsqrtf(var + 1e-5f);
#pragma unroll
    for (int i = 0; i < 3; i++) {
        int c = tid + i*256;
        float val = (v[i] - mu) * inv * g[c] + b[c];
        sx[c] = val;
        outb[(size_t)row*DD + c] = __float2bfloat16(val);
    }
    __syncthreads();
    // warp e computes logit e
    float acc = 0.f;
    const float* wr = w_router + warp*DD;
    for (int d = lane; d < DD; d += 32) acc += sx[d] * wr[d];
#pragma unroll
    for (int off = 16; off > 0; off >>= 1)
        acc += __shfl_down_sync(0xffffffffu, acc, off);
    if (lane == 0) slog[warp] = acc;
    __syncthreads();
    if (tid == 0) {
        float mx = slog[0];
#pragma unroll
        for (int e = 1; e < EE; e++) mx = fmaxf(mx, slog[e]);
        float ex[EE];
#pragma unroll
        for (int e = 0; e < EE; e++) ex[e] = expf(slog[e] - mx);
        int i0 = 0;
#pragma unroll
        for (int e = 1; e < EE; e++) if (ex[e] > ex[i0]) i0 = e;
        int i1 = (i0 == 0) ? 1 : 0;
#pragma unroll
        for (int e = 0; e < EE; e++) if (e != i0 && ex[e] > ex[i1]) i1 = e;
        float denom = ex[i0] + ex[i1];
        g_topidx[row*2+0] = i0;  g_topw[row*2+0] = ex[i0]/denom;
        g_topidx[row*2+1] = i1;  g_topw[row*2+1] = ex[i1]/denom;
        atomicAdd(&g_counts[i0], 1);
        atomicAdd(&g_counts[i1], 1);
    }
}

// ---------------- bf16 MMA GEMM: k-step 32, ldmatrix frags, 3-stage cp.async --------
// MODE 0: Cb = bf16(A@B + bias)                  (QKV)
// MODE 1: C = A@B + bias + resid; C2 = C (fp32)  (attn out proj + out init)
// MODE 2: Cb = bf16(gelu(gather(A)@B[e]+bias))   (MoE FC)
// MODE 3: atomic C[tok] += w*(A@B[e]+bias[e])    (MoE PROJ)
template<int MODE, int TM, int TN>
__global__ void __launch_bounds__(256)
mma_gemm(const __nv_bfloat16* __restrict__ A, const __nv_bfloat16* __restrict__ B,
         const float* __restrict__ bias, const float* __restrict__ resid,
         void* __restrict__ Cv, float* __restrict__ C2, int M, int N, int K) {
    constexpr int MI = TM/32;
    constexpr int NI = TN/32;
    constexpr int WCOL = TN/4;
    constexpr int APAD = 40;
    constexpr int BPAD = TN + 8;
    constexpr int ASTRIDE = TM*APAD;
    constexpr int BSTRIDE = 32*BPAD;
    constexpr int ACT = TM*4/256;
    constexpr int BCT = TN*4/256;

    int e = 0, seg = 0, cnt = M;
    if (MODE >= 2) {
        e = blockIdx.z;
        seg = g_offsets[e];
        cnt = g_offsets[e+1] - seg;
    }
    int rowBase = blockIdx.y * TM;
    if (rowBase >= cnt) return;
    int colBase = blockIdx.x * TN;
    const __nv_bfloat16* Bm = B + (size_t)e*K*N;
    const float* biasv = bias + (size_t)e*N;

    extern __shared__ __nv_bfloat16 smemb[];
    __nv_bfloat16* Asm = smemb;
    __nv_bfloat16* Bsm = smemb + 3*ASTRIDE;
    __shared__ int sTok[TM];

    int tid = threadIdx.x;
    int lane = tid & 31, warp = tid >> 5;
    int wy = warp >> 2, wx = warp & 3;
    int g4 = lane >> 2, t4 = lane & 3;

    if (MODE == 2) {
        for (int i = tid; i < TM; i += 256)
            sTok[i] = (rowBase + i < cnt) ? g_pairtok[seg + rowBase + i] : -1;
        __syncthreads();
    }

    int arow[ACT], akh[ACT];
    const __nv_bfloat16* aptr[ACT];
    bool avalid[ACT];
#pragma unroll
    for (int l = 0; l < ACT; l++) {
        int idx = tid + l*256;
        arow[l] = idx >> 2; akh[l] = (idx & 3) * 8;
        if (MODE == 2) {
            int tk = sTok[arow[l]];
            avalid[l] = (tk >= 0);
            aptr[l] = A + (avalid[l] ? (size_t)tk*K : 0) + akh[l];
        } else if (MODE == 3) {
            avalid[l] = (rowBase + arow[l] < cnt);
            aptr[l] = A + (avalid[l] ? (size_t)(seg + rowBase + arow[l])*K : 0) + akh[l];
        } else {
            avalid[l] = true;
            aptr[l] = A + (size_t)(rowBase + arow[l])*K + akh[l];
        }
    }
    int brow[BCT], bseg[BCT];
    const __nv_bfloat16* bptr[BCT];
#pragma unroll
    for (int l = 0; l < BCT; l++) {
        int idx = tid + l*256;
        brow[l] = idx / (TN/8); bseg[l] = (idx % (TN/8)) * 8;
        bptr[l] = Bm + (size_t)brow[l]*N + colBase + bseg[l];
    }

    float acc[MI][NI][4] = {};
    int nt = K / 32;

#pragma unroll
    for (int p = 0; p < 2; p++) {
        int k0 = p * 32;
#pragma unroll
        for (int l = 0; l < ACT; l++)
            cp16(&Asm[p*ASTRIDE + arow[l]*APAD + akh[l]], aptr[l] + k0, avalid[l]);
#pragma unroll
        for (int l = 0; l < BCT; l++)
            cp16(&Bsm[p*BSTRIDE + brow[l]*BPAD + bseg[l]], bptr[l] + (size_t)k0*N, true);
        cp_commit();
    }

    int lrow = lane & 15;
    int lcol = (lane >> 4) * 8;

    for (int kt = 0; kt < nt; kt++) {
        if (kt + 1 < nt) cp_wait1(); else cp_wait0();
        __syncthreads();
        if (kt + 2 < nt) {
            int st = (kt + 2) % 3;
            int k0 = (kt + 2) * 32;
#pragma unroll
            for (int l = 0; l < ACT; l++)
                cp16(&Asm[st*ASTRIDE + arow[l]*APAD + akh[l]], aptr[l] + k0, avalid[l]);
#pragma unroll
            for (int l = 0; l < BCT; l++)
                cp16(&Bsm[st*BSTRIDE + brow[l]*BPAD + bseg[l]], bptr[l] + (size_t)k0*N, true);
            cp_commit();
        }
        unsigned abase = (unsigned)__cvta_generic_to_shared(Asm + (kt % 3)*ASTRIDE);
        unsigned bbase = (unsigned)__cvta_generic_to_shared(Bsm + (kt % 3)*BSTRIDE);

#pragma unroll
        for (int ks = 0; ks < 32; ks += 16) {
            unsigned af[MI][4];
#pragma unroll
            for (int mi = 0; mi < MI; mi++) {
                unsigned addr = abase + ((wy*(TM/2) + mi*16 + lrow)*APAD + ks + lcol)*2;
                ldsm4(af[mi][0], af[mi][1], af[mi][2], af[mi][3], addr);
            }
            unsigned bf[NI][2];
#pragma unroll
            for (int nh = 0; nh < NI/2; nh++) {
                unsigned addr = bbase + ((ks + lrow)*BPAD + wx*WCOL + nh*16 + lcol)*2;
                ldsm4t(bf[nh*2][0], bf[nh*2][1], bf[nh*2+1][0], bf[nh*2+1][1], addr);
            }
#pragma unroll
            for (int mi = 0; mi < MI; mi++)
#pragma unroll
                for (int ni = 0; ni < NI; ni++)
                    mma_bf16(acc[mi][ni], af[mi][0], af[mi][1], af[mi][2], af[mi][3],
                             bf[ni][0], bf[ni][1]);
        }
    }

    __nv_bfloat16* Cb = (__nv_bfloat16*)Cv;
    float* C = (float*)Cv;
#pragma unroll
    for (int mi = 0; mi < MI; mi++) {
#pragma unroll
        for (int ci = 0; ci < 2; ci++) {
            int r = wy*(TM/2) + mi*16 + g4 + ci*8;
            int grow = rowBase + r;
            if (grow >= cnt) continue;
#pragma unroll
            for (int ni = 0; ni < NI; ni++) {
                int col = colBase + wx*WCOL + ni*8 + t4*2;
                float v0 = acc[mi][ni][ci*2 + 0];
                float v1 = acc[mi][ni][ci*2 + 1];
                if (MODE == 0) {
                    v0 += biasv[col]; v1 += biasv[col+1];
                    *(__nv_bfloat162*)&Cb[(size_t)grow*N + col] = __floats2bfloat162_rn(v0, v1);
                } else if (MODE == 1) {
                    const float2 rr = *(const float2*)&resid[(size_t)grow*N + col];
                    v0 += biasv[col]   + rr.x;
                    v1 += biasv[col+1] + rr.y;
                    *(float2*)&C [(size_t)grow*N + col] = make_float2(v0, v1);
                    *(float2*)&C2[(size_t)grow*N + col] = make_float2(v0, v1);
                } else if (MODE == 2) {
                    v0 += biasv[col]; v1 += biasv[col+1];
                    v0 = 0.5f*v0*(1.0f + erff(v0*0.70710678118654752f));
                    v1 = 0.5f*v1*(1.0f + erff(v1*0.70710678118654752f));
                    *(__nv_bfloat162*)&Cb[(size_t)(seg + grow)*N + col] = __floats2bfloat162_rn(v0, v1);
                } else {
                    int p = seg + grow;
                    int tok = g_pairtok[p];
                    float pw = g_pairw[p];
                    atomicAdd(&C[(size_t)tok*N + col],   pw*(v0 + biasv[col]));
                    atomicAdd(&C[(size_t)tok*N + col+1], pw*(v1 + biasv[col+1]));
                }
            }
        }
    }
}

// ---------------- bf16 tensor-core attention v2: P in registers, ldmatrix B-frags ------
// 128 threads = 4 warps; warp owns 16 query rows. smem K/V tiles [64][72] bf16.
// ldmatrix facts:
//   non-trans: thread T holds S[T/4][2(T%4)], S[T/4][2(T%4)+1]  (pair = consecutive cols)
//   trans:     thread T holds S[2(T%4)][T/4], S[2(T%4)+1][T/4]  (pair = consecutive rows)
//   mma B-frag pair must span consecutive k.
//   sK is n-major (rows=keys, cols=d=k)  -> pair spans cols -> NON-TRANS; tiles r0..r3 =
//     (n0-7,k0-7),(n8-15,k0-7),(n0-7,k8-15),(n8-15,k8-15) -> pairs (r0,r2),(r1,r3).
//   sV is k-major (rows=k, cols=d=n)     -> pair spans rows -> TRANS; pairs (r0,r1),(r2,r3).
__global__ void __launch_bounds__(128) attn_mma() {
    extern __shared__ __nv_bfloat16 sm16[];
    __nv_bfloat16* sK = sm16;             // [64][72]
    __nv_bfloat16* sV = sm16 + 64*72;     // [64][72]

    int tid = threadIdx.x;
    int lane = tid & 31, warp = tid >> 5;
    int g4 = lane >> 2, t4 = lane & 3;
    int lrow = lane & 15;
    int lcol = (lane >> 4) * 8;
    int qt = (gridDim.x - 1) - blockIdx.x;     // heavy tiles first
    int bh = blockIdx.y;
    int b = bh / HH, h = bh % HH;
    size_t base = (size_t)(b*SS)*D3 + h*HDIM;

    int qr0 = qt*64 + warp*16 + g4;
    int qr1 = qr0 + 8;

    // Q fragments (bf16, unscaled; 1/8 folded into logits)
    unsigned aq[4][4];
    const __nv_bfloat16* Qr0 = g_qkvb + base + (size_t)qr0*D3;
    const __nv_bfloat16* Qr1 = g_qkvb + base + (size_t)qr1*D3;
#pragma unroll
    for (int kb = 0; kb < 4; kb++) {
        aq[kb][0] = *(const unsigned*)&Qr0[kb*16 + 2*t4];
        aq[kb][1] = *(const unsigned*)&Qr1[kb*16 + 2*t4];
        aq[kb][2] = *(const unsigned*)&Qr0[kb*16 + 2*t4 + 8];
        aq[kb][3] = *(const unsigned*)&Qr1[kb*16 + 2*t4 + 8];
    }

    float m0 = -1e30f, m1 = -1e30f, l0 = 0.f, l1 = 0.f;
    float o[8][4] = {};

    for (int kt = 0; kt <= qt; kt++) {
        __syncthreads();
#pragma unroll
        for (int l = 0; l < 4; l++) {
            int idx = tid + l*128;
            int r = idx >> 3, c8 = (idx & 7) * 8;
            size_t rowp = base + (size_t)(kt*64 + r)*D3;
            *(uint4*)&sK[r*72 + c8] = *(const uint4*)&g_qkvb[rowp + DD + c8];
            *(uint4*)&sV[r*72 + c8] = *(const uint4*)&g_qkvb[rowp + 2*DD + c8];
        }
        __syncthreads();
        unsigned kbase = (unsigned)__cvta_generic_to_shared(sK);
        unsigned vbase = (unsigned)__cvta_generic_to_shared(sV);

        // S = Q K^T : sK n-major -> NON-TRANS ldmatrix, pairs (r0,r2)/(r1,r3)
        float s[8][4] = {};
#pragma unroll
        for (int kb = 0; kb < 4; kb++) {
#pragma unroll
            for (int nh = 0; nh < 4; nh++) {
                unsigned b0, b1, b2, b3;
                ldsm4(b0, b1, b2, b3,
                      kbase + ((nh*16 + lrow)*72 + kb*16 + lcol)*2);
                mma_bf16(s[nh*2],   aq[kb][0], aq[kb][1], aq[kb][2], aq[kb][3], b0, b2);
                mma_bf16(s[nh*2+1], aq[kb][0], aq[kb][1], aq[kb][2], aq[kb][3], b1, b3);
            }
        }
#pragma unroll
        for (int jt = 0; jt < 8; jt++)
#pragma unroll
            for (int c = 0; c < 4; c++) s[jt][c] *= 0.125f;

        if (kt == qt) {
            int lr0 = warp*16 + g4, lr1 = lr0 + 8;
#pragma unroll
            for (int jt = 0; jt < 8; jt++) {
                int c = jt*8 + t4*2;
                if (c     > lr0) s[jt][0] = -1e30f;
                if (c + 1 > lr0) s[jt][1] = -1e30f;
                if (c     > lr1) s[jt][2] = -1e30f;
                if (c + 1 > lr1) s[jt][3] = -1e30f;
            }
        }
        // online softmax (stats across thread-quad); s becomes P in-place
        float rm0 = -1e30f, rm1 = -1e30f;
#pragma unroll
        for (int jt = 0; jt < 8; jt++) {
            rm0 = fmaxf(rm0, fmaxf(s[jt][0], s[jt][1]));
            rm1 = fmaxf(rm1, fmaxf(s[jt][2], s[jt][3]));
        }
        rm0 = fmaxf(rm0, __shfl_xor_sync(0xffffffffu, rm0, 1));
        rm0 = fmaxf(rm0, __shfl_xor_sync(0xffffffffu, rm0, 2));
        rm1 = fmaxf(rm1, __shfl_xor_sync(0xffffffffu, rm1, 1));
        rm1 = fmaxf(rm1, __shfl_xor_sync(0xffffffffu, rm1, 2));
        float nm0 = fmaxf(m0, rm0), nm1 = fmaxf(m1, rm1);
        float sc0 = __expf(m0 - nm0), sc1 = __expf(m1 - nm1);
        float ps0 = 0.f, ps1 = 0.f;
#pragma unroll
        for (int jt = 0; jt < 8; jt++) {
            s[jt][0] = __expf(s[jt][0] - nm0);
            s[jt][1] = __expf(s[jt][1] - nm0);
            s[jt][2] = __expf(s[jt][2] - nm1);
            s[jt][3] = __expf(s[jt][3] - nm1);
            ps0 += s[jt][0] + s[jt][1];
            ps1 += s[jt][2] + s[jt][3];
        }
        ps0 += __shfl_xor_sync(0xffffffffu, ps0, 1);
        ps0 += __shfl_xor_sync(0xffffffffu, ps0, 2);
        ps1 += __shfl_xor_sync(0xffffffffu, ps1, 1);
        ps1 += __shfl_xor_sync(0xffffffffu, ps1, 2);
        l0 = l0*sc0 + ps0;  m0 = nm0;
        l1 = l1*sc1 + ps1;  m1 = nm1;
#pragma unroll
        for (int dt = 0; dt < 8; dt++) {
            o[dt][0] *= sc0; o[dt][1] *= sc0;
            o[dt][2] *= sc1; o[dt][3] *= sc1;
        }

        // O += P V : P packed from registers; sV k-major -> TRANS, pairs (r0,r1)/(r2,r3)
#pragma unroll
        for (int kb = 0; kb < 4; kb++) {
            unsigned ap0 = packbf(s[2*kb][0],   s[2*kb][1]);
            unsigned ap1 = packbf(s[2*kb][2],   s[2*kb][3]);
            unsigned ap2 = packbf(s[2*kb+1][0], s[2*kb+1][1]);
            unsigned ap3 = packbf(s[2*kb+1][2], s[2*kb+1][3]);
#pragma unroll
            for (int nh = 0; nh < 4; nh++) {
                unsigned b0, b1, b2, b3;
                ldsm4t(b0, b1, b2, b3,
                       vbase + ((kb*16 + lrow)*72 + nh*16 + lcol)*2);
                mma_bf16(o[nh*2],   ap0, ap1, ap2, ap3, b0, b1);
                mma_bf16(o[nh*2+1], ap0, ap1, ap2, ap3, b2, b3);
            }
        }
    }

    // write ctx (bf16)
    float inv0 = 1.0f / l0, inv1 = 1.0f / l1;
#pragma unroll
    for (int dt = 0; dt < 8; dt++) {
        int col = h*HDIM + dt*8 + t4*2;
        *(__nv_bfloat162*)&g_ctxb[(size_t)(b*SS + qr0)*DD + col] =
            __floats2bfloat162_rn(o[dt][0]*inv0, o[dt][1]*inv0);
        *(__nv_bfloat162*)&g_ctxb[(size_t)(b*SS + qr1)*DD + col] =
            __floats2bfloat162_rn(o[dt][2]*inv1, o[dt][3]*inv1);
    }
}

// ---------------- fused offsets + scatter (one block) ----------------
__global__ void scatter_kernel() {
    int tid = threadIdx.x;
    if (tid == 0) {
        g_offsets[0] = 0;
        for (int e = 0; e < EE; e++) {
            g_offsets[e+1] = g_offsets[e] + g_counts[e];
            g_cursor[e] = 0;
        }
    }
    __syncthreads();
    for (int t = tid; t < NTOK; t += blockDim.x) {
#pragma unroll
        for (int k = 0; k < TOPK; k++) {
            int e = g_topidx[t*2+k];
            int pos = g_offsets[e] + atomicAdd(&g_cursor[e], 1);
            g_pairtok[pos] = t;
            g_pairw[pos]   = g_topw[t*2+k];
        }
    }
}

// ---------------- launch ----------------
extern "C" void kernel_launch(void* const* d_in, const int* in_sizes, int n_in,
                              void* d_out, int out_size) {
    const float* hidden     = (const float*)d_in[0];
    const float* ln1_g      = (const float*)d_in[1];
    const float* ln1_b      = (const float*)d_in[2];
    const float* w_attn     = (const float*)d_in[3];
    const float* b_attn     = (const float*)d_in[4];
    const float* w_attnproj = (const float*)d_in[5];
    const float* b_attnproj = (const float*)d_in[6];
    const float* ln2_g      = (const float*)d_in[7];
    const float* ln2_b      = (const float*)d_in[8];
    const float* w_router   = (const float*)d_in[9];
    const float* w_fc       = (const float*)d_in[10];
    const float* b_fc       = (const float*)d_in[11];
    const float* w_proj     = (const float*)d_in[12];
    const float* b_proj     = (const float*)d_in[13];
    float* out = (float*)d_out;

    __nv_bfloat16 *xln1b, *qkvb, *ctxb, *x2b, *ghb;
    __nv_bfloat16 *wattnb, *waprojb, *wfcb, *wprojb;
    float *hs;
    int* counts;
    cudaGetSymbolAddress((void**)&xln1b,   g_xln1b);
    cudaGetSymbolAddress((void**)&qkvb,    g_qkvb);
    cudaGetSymbolAddress((void**)&ctxb,    g_ctxb);
    cudaGetSymbolAddress((void**)&hs,      g_hs);
    cudaGetSymbolAddress((void**)&x2b,     g_x2b);
    cudaGetSymbolAddress((void**)&ghb,     g_hb);
    cudaGetSymbolAddress((void**)&wattnb,  g_wattnb);
    cudaGetSymbolAddress((void**)&waprojb, g_waprojb);
    cudaGetSymbolAddress((void**)&wfcb,    g_wfcb);
    cudaGetSymbolAddress((void**)&wprojb,  g_wprojb);
    cudaGetSymbolAddress((void**)&counts,  g_counts);

    const int SM128 = 3*(128*40 + 32*136)*2;  // 56832
    const int SM64  = 3*(64*40  + 32*136)*2;  // 41472
    const int SMATT = 2*64*72*2;              // 18432

    cudaFuncSetAttribute((const void*)mma_gemm<0,128,128>, cudaFuncAttributeMaxDynamicSharedMemorySize, SM128);
    cudaFuncSetAttribute((const void*)mma_gemm<1,64,128>,  cudaFuncAttributeMaxDynamicSharedMemorySize, SM64);
    cudaFuncSetAttribute((const void*)mma_gemm<2,128,128>, cudaFuncAttributeMaxDynamicSharedMemorySize, SM128);
    cudaFuncSetAttribute((const void*)mma_gemm<3,64,128>,  cudaFuncAttributeMaxDynamicSharedMemorySize, SM64);

    // side stream + events
    static cudaStream_t s2 = nullptr;
    static cudaEvent_t evFork = nullptr, evJoin = nullptr;
    if (!s2) {
        cudaStreamCreateWithFlags(&s2, cudaStreamNonBlocking);
        cudaEventCreateWithFlags(&evFork, cudaEventDisableTiming);
        cudaEventCreateWithFlags(&evJoin, cudaEventDisableTiming);
    }

    auto cvtgrid = [](int n4) { int g = (n4 + 255)/256; return g < 1184 ? g : 1184; };

    // fork: big MoE weight conversions overlapped with attention phase
    cudaEventRecord(evFork, 0);
    cudaStreamWaitEvent(s2, evFork, 0);
    cvt_bf16<<<cvtgrid(EE*DD*FF/4), 256, 0, s2>>>((const float4*)w_fc, (uint2*)wfcb, EE*DD*FF/4);
    cvt_bf16<<<cvtgrid(EE*FF*DD/4), 256, 0, s2>>>((const float4*)w_proj, (uint2*)wprojb, EE*FF*DD/4);
    cudaEventRecord(evJoin, s2);

    // main stream: small conversions + attention sub-block
    cvt_bf16<<<cvtgrid(DD*D3/4), 256>>>((const float4*)w_attn, (uint2*)wattnb, DD*D3/4);
    cvt_bf16<<<cvtgrid(DD*DD/4), 256>>>((const float4*)w_attnproj, (uint2*)waprojb, DD*DD/4);
    ln_kernel<<<NTOK, 256>>>(hidden, ln1_g, ln1_b, xln1b);
    mma_gemm<0,128,128><<<dim3(D3/128, NTOK/128, 1), 256, SM128>>>(
        xln1b, wattnb, b_attn, nullptr, qkvb, nullptr, NTOK, D3, DD);
    attn_mma<<<dim3(SS/64, BB*HH), 128, SMATT>>>();
    mma_gemm<1,64,128><<<dim3(DD/128, NTOK/64, 1), 256, SM64>>>(
        ctxb, waprojb, b_attnproj, hidden, hs, out, NTOK, DD, DD);

    // MoE routing (LN2 + router fused)
    cudaMemsetAsync(counts, 0, EE*sizeof(int));
    ln2_router_kernel<<<NTOK, 256>>>(hs, ln2_g, ln2_b, x2b, w_router);
    scatter_kernel<<<1, 256>>>();

    // join: FC/PROJ need the converted MoE weights
    cudaStreamWaitEvent(0, evJoin, 0);
    mma_gemm<2,128,128><<<dim3(FF/128, NPAIR/128, EE), 256, SM128>>>(
        x2b, wfcb, b_fc, nullptr, ghb, nullptr, NPAIR, FF, DD);
    mma_gemm<3,64,128><<<dim3(DD/128, NPAIR/64, EE), 256, SM64>>>(
        ghb, wprojb, b_proj, nullptr, out, nullptr, NPAIR, DD, FF);
}